// round 14
// baseline (speedup 1.0000x reference)
#include <cuda_runtime.h>
#include <cuda_bf16.h>
#include <math.h>

#define Bz   32
#define Tz   512
#define INz  256
#define Hz   1024
#define G4z  4096
#define OUTz 256
#define Mz   (Bz * Tz)          // 16384

#define RBLK  128                // recurrent blocks (1/SM, all co-resident)
#define SLOTS 64                 // k16 slots covering Hz=1024
#define RWARPS 16                // warps in lstm_rec (512 threads)

// lstm_rec smem: Wfrag uint4[64*4*32] (131072 B) + Psm f32[16*32*36] (73728 B)
//                + Gsm f32[32*36] (4608 B)
#define SMEM_REC  (131072 + 73728 + 4608)     // 209408 B

#define GEMM_SMEM (2 * 2 * 128 * 36 * 4)      // 73728 B

// ------------------------- device scratch (no allocs allowed) -------------------
static __device__ float  g_xw [(size_t)Mz * G4z];   // 256 MB
static __device__ float  g_hs0[(size_t)Mz * Hz];    // 64 MB
static __device__ float  g_hs1[(size_t)Mz * Hz];    // 64 MB
// h in MMA A-fragment layout: [parity][slot][mt][plane hi/lo][lane] = uint4
static __device__ uint4    g_frag[2][SLOTS][2][2][32];
static __device__ unsigned g_arrive[RBLK];
static __device__ unsigned g_gen2;

// ---------------------------------------------------------------------------------
// tf32 tensor-core GEMM — unchanged from R12 (verified).
// ---------------------------------------------------------------------------------
__device__ __forceinline__ unsigned f2tf(float f) {
    unsigned u; asm("cvt.rna.tf32.f32 %0, %1;" : "=r"(u) : "f"(f)); return u;
}

#define MMA_TF32(d, a, b)                                                     \
    asm volatile("mma.sync.aligned.m16n8k8.row.col.f32.tf32.tf32.f32 "        \
        "{%0,%1,%2,%3}, {%4,%5,%6,%7}, {%8,%9}, {%0,%1,%2,%3};"               \
        : "+f"(d[0]), "+f"(d[1]), "+f"(d[2]), "+f"(d[3])                      \
        : "r"(a[0]), "r"(a[1]), "r"(a[2]), "r"(a[3]), "r"(b[0]), "r"(b[1]))

__global__ void __launch_bounds__(256) gemm_tf32(
    const float* __restrict__ A, const float* __restrict__ W,
    const float* __restrict__ bias1, const float* __restrict__ bias2,
    float* __restrict__ O, int N, int K, int amode, int omode)
{
    extern __shared__ unsigned gsm[];
    unsigned* Asm = gsm;
    unsigned* Bsm = gsm + 2 * 128 * 36;

    const int tid  = threadIdx.x;
    const int bm   = blockIdx.y * 128;
    const int bn   = blockIdx.x * 128;
    const int wid  = tid >> 5, lane = tid & 31;
    const int wm   = (wid >> 2) * 64;
    const int wn   = (wid & 3) * 32;
    const int g    = lane >> 2;
    const int t4   = lane & 3;

    const int lr = tid >> 1;
    const int lh = (tid & 1) * 16;

    long arow;
    {
        const int m = bm + lr;
        if (amode == 1) { const int b = m & 31, t = m >> 5; arow = ((long)b * Tz + t) * (long)K; }
        else            { arow = (long)m * K; }
    }
    const long brow = (long)(bn + lr) * K;

    float acc[4][4][4];
#pragma unroll
    for (int i = 0; i < 4; i++)
#pragma unroll
        for (int j = 0; j < 4; j++)
#pragma unroll
            for (int q = 0; q < 4; q++) acc[i][j][q] = 0.f;

    float4 av[4], bv[4];
#pragma unroll
    for (int q = 0; q < 4; q++) {
        av[q] = __ldg((const float4*)(A + arow + lh + q * 4));
        bv[q] = __ldg((const float4*)(W + brow + lh + q * 4));
    }

    const int nc = K >> 5;
    for (int c = 0; c < nc; c++) {
        unsigned* as = Asm + (c & 1) * (128 * 36);
        unsigned* bs = Bsm + (c & 1) * (128 * 36);
        const int sb = lr * 36 + lh;
#pragma unroll
        for (int q = 0; q < 4; q++) {
            uint4 ua = make_uint4(f2tf(av[q].x), f2tf(av[q].y), f2tf(av[q].z), f2tf(av[q].w));
            uint4 ub = make_uint4(f2tf(bv[q].x), f2tf(bv[q].y), f2tf(bv[q].z), f2tf(bv[q].w));
            *(uint4*)&as[sb + q * 4] = ua;
            *(uint4*)&bs[sb + q * 4] = ub;
        }
        __syncthreads();

        if (c + 1 < nc) {
            const long ko = (long)(c + 1) * 32 + lh;
#pragma unroll
            for (int q = 0; q < 4; q++) {
                av[q] = __ldg((const float4*)(A + arow + ko + q * 4));
                bv[q] = __ldg((const float4*)(W + brow + ko + q * 4));
            }
        }

#pragma unroll
        for (int k8 = 0; k8 < 32; k8 += 8) {
            unsigned af[4][4], bf[4][2];
#pragma unroll
            for (int fm = 0; fm < 4; fm++) {
                const int r0 = wm + fm * 16 + g;
                af[fm][0] = as[r0 * 36 + k8 + t4];
                af[fm][1] = as[(r0 + 8) * 36 + k8 + t4];
                af[fm][2] = as[r0 * 36 + k8 + t4 + 4];
                af[fm][3] = as[(r0 + 8) * 36 + k8 + t4 + 4];
            }
#pragma unroll
            for (int fn = 0; fn < 4; fn++) {
                const int n0 = wn + fn * 8 + g;
                bf[fn][0] = bs[n0 * 36 + k8 + t4];
                bf[fn][1] = bs[n0 * 36 + k8 + t4 + 4];
            }
#pragma unroll
            for (int fm = 0; fm < 4; fm++)
#pragma unroll
                for (int fn = 0; fn < 4; fn++)
                    MMA_TF32(acc[fm][fn], af[fm], bf[fn]);
        }
        // no trailing sync: double buffer + store->sync->compute ordering is race-free
    }

#pragma unroll
    for (int fm = 0; fm < 4; fm++) {
        const int r0 = bm + wm + fm * 16 + g;
#pragma unroll
        for (int fn = 0; fn < 4; fn++) {
            const int n0 = bn + wn + fn * 8 + t4 * 2;
            float b0v = bias1[n0], b1v = bias1[n0 + 1];
            if (bias2) { b0v += bias2[n0]; b1v += bias2[n0 + 1]; }
            const float2 v0 = make_float2(acc[fm][fn][0] + b0v, acc[fm][fn][1] + b1v);
            const float2 v1 = make_float2(acc[fm][fn][2] + b0v, acc[fm][fn][3] + b1v);
            if (omode == 0) {
                *(float2*)&O[(long)r0 * N + n0]       = v0;
                *(float2*)&O[(long)(r0 + 8) * N + n0] = v1;
            } else {
                int b_ = r0 & 31, t_ = r0 >> 5;
                *(float2*)&O[((long)b_ * Tz + t_) * N + n0] = v0;
                b_ = (r0 + 8) & 31; t_ = (r0 + 8) >> 5;
                *(float2*)&O[((long)b_ * Tz + t_) * N + n0] = v1;
            }
        }
    }
}

// ---------------------------------------------------------------------------------
// Persistent LSTM recurrence — 16 warps (512 threads), warp w owns k range
// [w*64, (w+1)*64) (4 slots). Same two-hop barrier, 3-term bf16 split.
// ---------------------------------------------------------------------------------
__device__ __forceinline__ float sigm(float x) {
    return __fdividef(1.0f, 1.0f + __expf(-x));
}
__device__ __forceinline__ float tanh_fast(float x) {
    const float e = __expf(2.0f * x);
    return __fdividef(e - 1.0f, e + 1.0f);
}

__device__ __forceinline__ unsigned packbf2(__nv_bfloat16 a, __nv_bfloat16 b) {
    return (unsigned)__bfloat16_as_ushort(a) | ((unsigned)__bfloat16_as_ushort(b) << 16);
}

#define MMA_BF16(d, a0, a1, a2, a3, b0, b1)                                   \
    asm volatile("mma.sync.aligned.m16n8k16.row.col.f32.bf16.bf16.f32 "       \
        "{%0,%1,%2,%3}, {%4,%5,%6,%7}, {%8,%9}, {%0,%1,%2,%3};"               \
        : "+f"(d[0]), "+f"(d[1]), "+f"(d[2]), "+f"(d[3])                      \
        : "r"(a0), "r"(a1), "r"(a2), "r"(a3), "r"(b0), "r"(b1))

__global__ void __launch_bounds__(512, 1) lstm_rec(
    const float* __restrict__ xw,      // [T*B][4096], row m = t*32+b
    const float* __restrict__ Whh,     // [4096][1024]
    float* __restrict__ hs_out)        // [T*B][1024], row m = t*32+b
{
    extern __shared__ char smraw[];
    uint4* Wfrag = (uint4*)smraw;                 // [64 slots][4 nt][32 lanes]
    float* Psm   = (float*)(smraw + 131072);      // [16 w][32 b][36]
    float* Gsm   = Psm + RWARPS * 32 * 36;        // [32 b][36 n]
    __shared__ unsigned s_base;

    const int tid  = threadIdx.x;
    const int bid  = blockIdx.x;
    const int u0   = bid * 8;
    const int w    = tid >> 5;          // 0..15
    const int lane = tid & 31;
    const int g    = lane >> 2;
    const int th4  = lane & 3;

    // reduce mapping (512 threads, float2 each): batch rb, n pair rn2
    const int rb   = tid >> 4;           // 0..31
    const int rn2  = (tid & 15) * 2;     // 0,2,...,30
    const long xcol = (long)(rn2 >> 3) * 1024 + u0 + (rn2 & 7);

    // cell mapping (threads 0..255)
    const int cj = (tid >> 5) & 7, cb = tid & 31;
    // publish addressing for element (b=cb, k=u0+cj)
    const int pk    = u0 + cj;
    const int pslot = pk >> 4;
    const int pkk   = pk & 15;
    const int pt    = (pkk >> 1) & 3;
    const int pkreg = pkk >> 3;
    const int pbyte = pkk & 1;
    const int pmt   = cb >> 4;
    const int prh   = (cb >> 3) & 1;
    const int plane_idx = (cb & 7) * 4 + pt;
    const int preg  = pkreg * 2 + prh;

    // ---- one-time: pack W_hh rows into B-fragment smem (hi/lo bf16) ----
    // 512 threads: each handles one bf16 pair (2 k-values) per row n.
    {
        const int k0   = tid * 2;            // 0..1022, even
        const int s    = k0 >> 4;
        const int kk   = k0 & 15;
        const int tq   = (kk >> 1) & 3;
        const int kreg = kk >> 3;
        for (int n = 0; n < 32; n++) {
            const long grow = (long)(n >> 3) * 1024 + u0 + (n & 7);
            const float2 v = __ldg((const float2*)(Whh + grow * 1024 + k0));
            const int nt = n >> 3, gg = n & 7;
            const __nv_bfloat16 ah = __float2bfloat16(v.x);
            const __nv_bfloat16 bh = __float2bfloat16(v.y);
            const __nv_bfloat16 al = __float2bfloat16(v.x - __bfloat162float(ah));
            const __nv_bfloat16 bl = __float2bfloat16(v.y - __bfloat162float(bh));
            unsigned* wp = (unsigned*)&Wfrag[(s * 4 + nt) * 32 + gg * 4 + tq];
            wp[kreg]     = packbf2(ah, bh);
            wp[2 + kreg] = packbf2(al, bl);
        }
    }
    if (tid == 0) s_base = *(volatile unsigned*)&g_gen2;
    __syncthreads();
    const unsigned base = s_base;

    float cst = 0.f;

#pragma unroll 1
    for (int t = 0; t < Tz; t++) {
        const float2 xwv = __ldg((const float2*)(xw + ((long)t * 32 + rb) * 4096 + xcol));

        if (t > 0) {
            const int par = (t + 1) & 1;     // buffer where h(t-1) was published

            float acc[2][4][4];
#pragma unroll
            for (int mt = 0; mt < 2; mt++)
#pragma unroll
                for (int nt = 0; nt < 4; nt++)
#pragma unroll
                    for (int q = 0; q < 4; q++) acc[mt][nt][q] = 0.f;

            const int s0 = w * 4;
            // 2-deep A-fragment prefetch ring (4 slots total per warp)
            uint4 bAh[2][2], bAl[2][2];
#pragma unroll
            for (int pb = 0; pb < 2; pb++) {
                bAh[pb][0] = __ldcg(&g_frag[par][s0 + pb][0][0][lane]);
                bAh[pb][1] = __ldcg(&g_frag[par][s0 + pb][1][0][lane]);
                bAl[pb][0] = __ldcg(&g_frag[par][s0 + pb][0][1][lane]);
                bAl[pb][1] = __ldcg(&g_frag[par][s0 + pb][1][1][lane]);
            }

#pragma unroll
            for (int i = 0; i < 4; i++) {
                const int s   = s0 + i;
                const int buf = i & 1;
                uint4 Bf[4];
#pragma unroll
                for (int nt = 0; nt < 4; nt++)
                    Bf[nt] = Wfrag[(s * 4 + nt) * 32 + lane];

                const uint4 cAh0 = bAh[buf][0], cAh1 = bAh[buf][1];
                const uint4 cAl0 = bAl[buf][0], cAl1 = bAl[buf][1];
                if (i < 2) {
                    bAh[buf][0] = __ldcg(&g_frag[par][s + 2][0][0][lane]);
                    bAh[buf][1] = __ldcg(&g_frag[par][s + 2][1][0][lane]);
                    bAl[buf][0] = __ldcg(&g_frag[par][s + 2][0][1][lane]);
                    bAl[buf][1] = __ldcg(&g_frag[par][s + 2][1][1][lane]);
                }

#pragma unroll
                for (int nt = 0; nt < 4; nt++) {
                    MMA_BF16(acc[0][nt], cAh0.x, cAh0.y, cAh0.z, cAh0.w, Bf[nt].x, Bf[nt].y);
                    MMA_BF16(acc[1][nt], cAh1.x, cAh1.y, cAh1.z, cAh1.w, Bf[nt].x, Bf[nt].y);
                    MMA_BF16(acc[0][nt], cAl0.x, cAl0.y, cAl0.z, cAl0.w, Bf[nt].x, Bf[nt].y);
                    MMA_BF16(acc[1][nt], cAl1.x, cAl1.y, cAl1.z, cAl1.w, Bf[nt].x, Bf[nt].y);
                    MMA_BF16(acc[0][nt], cAh0.x, cAh0.y, cAh0.z, cAh0.w, Bf[nt].z, Bf[nt].w);
                    MMA_BF16(acc[1][nt], cAh1.x, cAh1.y, cAh1.z, cAh1.w, Bf[nt].z, Bf[nt].w);
                }
            }

            // per-warp partials -> Psm[w][b][n]
#pragma unroll
            for (int mt = 0; mt < 2; mt++) {
                const int b1 = mt * 16 + g, b2 = b1 + 8;
#pragma unroll
                for (int nt = 0; nt < 4; nt++) {
                    const int n0 = nt * 8 + 2 * th4;
                    *(float2*)&Psm[(w * 32 + b1) * 36 + n0] = make_float2(acc[mt][nt][0], acc[mt][nt][1]);
                    *(float2*)&Psm[(w * 32 + b2) * 36 + n0] = make_float2(acc[mt][nt][2], acc[mt][nt][3]);
                }
            }
        }
        __syncthreads();

        // reduce 16 warp partials + xw -> Gsm[b][n] (512 threads, float2 each)
        float2 sum = xwv;
        if (t > 0) {
#pragma unroll
            for (int s = 0; s < RWARPS; s++) {
                const float2 v = *(const float2*)&Psm[(s * 32 + rb) * 36 + rn2];
                sum.x += v.x; sum.y += v.y;
            }
        }
        *(float2*)&Gsm[rb * 36 + rn2] = sum;
        __syncthreads();

        // cell update (threads 0..255)
        float hf = 0.f;
        if (tid < 256) {
            const float gi = sigm     (Gsm[cb * 36 + cj]);
            const float gf = sigm     (Gsm[cb * 36 + 8 + cj]);
            const float gg2= tanh_fast(Gsm[cb * 36 + 16 + cj]);
            const float go = sigm     (Gsm[cb * 36 + 24 + cj]);
            cst = gf * cst + gi * gg2;
            hf = go * tanh_fast(cst);

            // publish h into fragment buffer (hi + lo planes)
            const __nv_bfloat16 hh = __float2bfloat16(hf);
            const __nv_bfloat16 hl = __float2bfloat16(hf - __bfloat162float(hh));
            const int par = t & 1;
            unsigned short* bhi = (unsigned short*)&g_frag[par][pslot][pmt][0][plane_idx];
            unsigned short* blo = (unsigned short*)&g_frag[par][pslot][pmt][1][plane_idx];
            bhi[preg * 2 + pbyte] = __bfloat16_as_ushort(hh);
            blo[preg * 2 + pbyte] = __bfloat16_as_ushort(hl);
        }

        // ---- grid barrier (two-hop flag barrier — proven optimum) ----
        const unsigned target = base + (unsigned)t + 1u;
        __threadfence();
        __syncthreads();
        if (tid == 0)
            *(volatile unsigned*)&g_arrive[bid] = target;
        if (bid == 0) {
            if (tid < RBLK) {
                while ((int)(*(volatile unsigned*)&g_arrive[tid] - target) < 0) {}
            }
            __syncthreads();
            if (tid == 0) {
                __threadfence();
                *(volatile unsigned*)&g_gen2 = target;
            }
        }
        if (tid == 0) {
            while ((int)(*(volatile unsigned*)&g_gen2 - target) < 0) {}
        }
        __syncthreads();

        // fp32 hidden state store off the critical path (after barrier)
        if (tid < 256)
            hs_out[((long)t * 32 + cb) * 1024 + u0 + cj] = hf;
    }
}

// ---------------------------------------------------------------------------------
extern "C" void kernel_launch(void* const* d_in, const int* in_sizes, int n_in,
                              void* d_out, int out_size)
{
    const float* x     = (const float*)d_in[0];
    const float* W_ih0 = (const float*)d_in[1];
    const float* W_hh0 = (const float*)d_in[2];
    const float* b_ih0 = (const float*)d_in[3];
    const float* b_hh0 = (const float*)d_in[4];
    const float* W_ih1 = (const float*)d_in[5];
    const float* W_hh1 = (const float*)d_in[6];
    const float* b_ih1 = (const float*)d_in[7];
    const float* b_hh1 = (const float*)d_in[8];
    const float* fc_w  = (const float*)d_in[9];
    const float* fc_b  = (const float*)d_in[10];
    float* out = (float*)d_out;

    float *xw, *hs0, *hs1;
    cudaGetSymbolAddress((void**)&xw,  g_xw);
    cudaGetSymbolAddress((void**)&hs0, g_hs0);
    cudaGetSymbolAddress((void**)&hs1, g_hs1);

    cudaFuncSetAttribute(lstm_rec, cudaFuncAttributeMaxDynamicSharedMemorySize, SMEM_REC);
    cudaFuncSetAttribute(gemm_tf32, cudaFuncAttributeMaxDynamicSharedMemorySize, GEMM_SMEM);

    // 1) xW0 = x @ W_ih0^T + b_ih0 + b_hh0        [16384 x 4096], K=256
    gemm_tf32<<<dim3(G4z / 128, Mz / 128), 256, GEMM_SMEM>>>(
        x, W_ih0, b_ih0, b_hh0, xw, G4z, INz, /*amode=*/1, /*omode=*/0);
    // 2) layer-0 recurrence -> hs0
    lstm_rec<<<RBLK, 512, SMEM_REC>>>(xw, W_hh0, hs0);
    // 3) xW1 = hs0 @ W_ih1^T + b_ih1 + b_hh1      [16384 x 4096], K=1024
    gemm_tf32<<<dim3(G4z / 128, Mz / 128), 256, GEMM_SMEM>>>(
        hs0, W_ih1, b_ih1, b_hh1, xw, G4z, Hz, /*amode=*/0, /*omode=*/0);
    // 4) layer-1 recurrence -> hs1
    lstm_rec<<<RBLK, 512, SMEM_REC>>>(xw, W_hh1, hs1);
    // 5) out = hs1 @ fc_w^T + fc_b                [b][t][256], K=1024
    gemm_tf32<<<dim3(OUTz / 128, Mz / 128), 256, GEMM_SMEM>>>(
        hs1, fc_w, fc_b, nullptr, out, OUTz, Hz, /*amode=*/0, /*omode=*/1);
}

// round 15
// speedup vs baseline: 1.1451x; 1.1451x over previous
#include <cuda_runtime.h>
#include <cuda_bf16.h>
#include <cuda_fp16.h>
#include <math.h>

#define Bz   32
#define Tz   512
#define INz  256
#define Hz   1024
#define G4z  4096
#define OUTz 256
#define Mz   (Bz * Tz)          // 16384

#define RBLK  128                // recurrent blocks (1/SM, all co-resident)
#define SLOTS 64                 // k16 slots covering Hz=1024

// lstm_rec smem: Wfrag uint4[64*4*32] (131072 B) + Psm f32[8*32*36] (36864 B)
//                + Gsm f32[32*36] (4608 B)
#define SMEM_REC  (131072 + 36864 + 4608)     // 172544 B

#define GEMM_SMEM (2 * 2 * 128 * 36 * 4)      // 73728 B

// ------------------------- device scratch (no allocs allowed) -------------------
static __device__ float  g_xw [(size_t)Mz * G4z];   // 256 MB
static __device__ float  g_hs0[(size_t)Mz * Hz];    // 64 MB
static __device__ float  g_hs1[(size_t)Mz * Hz];    // 64 MB
// h (fp16, single plane) in MMA A-fragment layout: [parity][slot][mt][lane]
static __device__ uint4    g_frag[2][SLOTS][2][32];
static __device__ unsigned g_arrive[RBLK];
static __device__ unsigned g_gen2;

// ---------------------------------------------------------------------------------
// tf32 tensor-core GEMM — unchanged from R12 (verified).
// ---------------------------------------------------------------------------------
__device__ __forceinline__ unsigned f2tf(float f) {
    unsigned u; asm("cvt.rna.tf32.f32 %0, %1;" : "=r"(u) : "f"(f)); return u;
}

#define MMA_TF32(d, a, b)                                                     \
    asm volatile("mma.sync.aligned.m16n8k8.row.col.f32.tf32.tf32.f32 "        \
        "{%0,%1,%2,%3}, {%4,%5,%6,%7}, {%8,%9}, {%0,%1,%2,%3};"               \
        : "+f"(d[0]), "+f"(d[1]), "+f"(d[2]), "+f"(d[3])                      \
        : "r"(a[0]), "r"(a[1]), "r"(a[2]), "r"(a[3]), "r"(b[0]), "r"(b[1]))

__global__ void __launch_bounds__(256) gemm_tf32(
    const float* __restrict__ A, const float* __restrict__ W,
    const float* __restrict__ bias1, const float* __restrict__ bias2,
    float* __restrict__ O, int N, int K, int amode, int omode)
{
    extern __shared__ unsigned gsm[];
    unsigned* Asm = gsm;
    unsigned* Bsm = gsm + 2 * 128 * 36;

    const int tid  = threadIdx.x;
    const int bm   = blockIdx.y * 128;
    const int bn   = blockIdx.x * 128;
    const int wid  = tid >> 5, lane = tid & 31;
    const int wm   = (wid >> 2) * 64;
    const int wn   = (wid & 3) * 32;
    const int g    = lane >> 2;
    const int t4   = lane & 3;

    const int lr = tid >> 1;
    const int lh = (tid & 1) * 16;

    long arow;
    {
        const int m = bm + lr;
        if (amode == 1) { const int b = m & 31, t = m >> 5; arow = ((long)b * Tz + t) * (long)K; }
        else            { arow = (long)m * K; }
    }
    const long brow = (long)(bn + lr) * K;

    float acc[4][4][4];
#pragma unroll
    for (int i = 0; i < 4; i++)
#pragma unroll
        for (int j = 0; j < 4; j++)
#pragma unroll
            for (int q = 0; q < 4; q++) acc[i][j][q] = 0.f;

    float4 av[4], bv[4];
#pragma unroll
    for (int q = 0; q < 4; q++) {
        av[q] = __ldg((const float4*)(A + arow + lh + q * 4));
        bv[q] = __ldg((const float4*)(W + brow + lh + q * 4));
    }

    const int nc = K >> 5;
    for (int c = 0; c < nc; c++) {
        unsigned* as = Asm + (c & 1) * (128 * 36);
        unsigned* bs = Bsm + (c & 1) * (128 * 36);
        const int sb = lr * 36 + lh;
#pragma unroll
        for (int q = 0; q < 4; q++) {
            uint4 ua = make_uint4(f2tf(av[q].x), f2tf(av[q].y), f2tf(av[q].z), f2tf(av[q].w));
            uint4 ub = make_uint4(f2tf(bv[q].x), f2tf(bv[q].y), f2tf(bv[q].z), f2tf(bv[q].w));
            *(uint4*)&as[sb + q * 4] = ua;
            *(uint4*)&bs[sb + q * 4] = ub;
        }
        __syncthreads();

        if (c + 1 < nc) {
            const long ko = (long)(c + 1) * 32 + lh;
#pragma unroll
            for (int q = 0; q < 4; q++) {
                av[q] = __ldg((const float4*)(A + arow + ko + q * 4));
                bv[q] = __ldg((const float4*)(W + brow + ko + q * 4));
            }
        }

#pragma unroll
        for (int k8 = 0; k8 < 32; k8 += 8) {
            unsigned af[4][4], bf[4][2];
#pragma unroll
            for (int fm = 0; fm < 4; fm++) {
                const int r0 = wm + fm * 16 + g;
                af[fm][0] = as[r0 * 36 + k8 + t4];
                af[fm][1] = as[(r0 + 8) * 36 + k8 + t4];
                af[fm][2] = as[r0 * 36 + k8 + t4 + 4];
                af[fm][3] = as[(r0 + 8) * 36 + k8 + t4 + 4];
            }
#pragma unroll
            for (int fn = 0; fn < 4; fn++) {
                const int n0 = wn + fn * 8 + g;
                bf[fn][0] = bs[n0 * 36 + k8 + t4];
                bf[fn][1] = bs[n0 * 36 + k8 + t4 + 4];
            }
#pragma unroll
            for (int fm = 0; fm < 4; fm++)
#pragma unroll
                for (int fn = 0; fn < 4; fn++)
                    MMA_TF32(acc[fm][fn], af[fm], bf[fn]);
        }
        // no trailing sync: double buffer + store->sync->compute ordering is race-free
    }

#pragma unroll
    for (int fm = 0; fm < 4; fm++) {
        const int r0 = bm + wm + fm * 16 + g;
#pragma unroll
        for (int fn = 0; fn < 4; fn++) {
            const int n0 = bn + wn + fn * 8 + t4 * 2;
            float b0v = bias1[n0], b1v = bias1[n0 + 1];
            if (bias2) { b0v += bias2[n0]; b1v += bias2[n0 + 1]; }
            const float2 v0 = make_float2(acc[fm][fn][0] + b0v, acc[fm][fn][1] + b1v);
            const float2 v1 = make_float2(acc[fm][fn][2] + b0v, acc[fm][fn][3] + b1v);
            if (omode == 0) {
                *(float2*)&O[(long)r0 * N + n0]       = v0;
                *(float2*)&O[(long)(r0 + 8) * N + n0] = v1;
            } else {
                int b_ = r0 & 31, t_ = r0 >> 5;
                *(float2*)&O[((long)b_ * Tz + t_) * N + n0] = v0;
                b_ = (r0 + 8) & 31; t_ = (r0 + 8) >> 5;
                *(float2*)&O[((long)b_ * Tz + t_) * N + n0] = v1;
            }
        }
    }
}

// ---------------------------------------------------------------------------------
// Persistent LSTM recurrence — R12 structure (8 warps, two-hop barrier, 3-deep A
// prefetch) with 2-term fp16 split: D = Whi_f16 @ h_f16 + Wlo_f16 @ h_f16.
// h quantized to fp16 (safe: |h|<1); W split error ~2^-22. 128 MMAs/warp/step.
// Adds 2-deep B-fragment (smem) prefetch ring.
// ---------------------------------------------------------------------------------
__device__ __forceinline__ float sigm(float x) {
    return __fdividef(1.0f, 1.0f + __expf(-x));
}
__device__ __forceinline__ float tanh_fast(float x) {
    const float e = __expf(2.0f * x);
    return __fdividef(e - 1.0f, e + 1.0f);
}

__device__ __forceinline__ unsigned packh2(__half a, __half b) {
    return (unsigned)__half_as_ushort(a) | ((unsigned)__half_as_ushort(b) << 16);
}

#define MMA_F16(d, a0, a1, a2, a3, b0, b1)                                    \
    asm volatile("mma.sync.aligned.m16n8k16.row.col.f32.f16.f16.f32 "         \
        "{%0,%1,%2,%3}, {%4,%5,%6,%7}, {%8,%9}, {%0,%1,%2,%3};"               \
        : "+f"(d[0]), "+f"(d[1]), "+f"(d[2]), "+f"(d[3])                      \
        : "r"(a0), "r"(a1), "r"(a2), "r"(a3), "r"(b0), "r"(b1))

__global__ void __launch_bounds__(256, 1) lstm_rec(
    const float* __restrict__ xw,      // [T*B][4096], row m = t*32+b
    const float* __restrict__ Whh,     // [4096][1024]
    float* __restrict__ hs_out)        // [T*B][1024], row m = t*32+b
{
    extern __shared__ char smraw[];
    uint4* Wfrag = (uint4*)smraw;                 // [64 slots][4 nt][32 lanes]
    float* Psm   = (float*)(smraw + 131072);      // [8 w][32 b][36]
    float* Gsm   = Psm + 8 * 32 * 36;             // [32 b][36 n]
    __shared__ unsigned s_base;

    const int tid  = threadIdx.x;
    const int bid  = blockIdx.x;
    const int u0   = bid * 8;
    const int w    = tid >> 5;
    const int lane = tid & 31;
    const int g    = lane >> 2;
    const int th4  = lane & 3;

    // reduce mapping
    const int rb   = tid >> 3;           // batch 0..31
    const int rn4  = (tid & 7) * 4;      // n group
    const long xcol = (long)(rn4 >> 3) * 1024 + u0 + (rn4 & 7);

    // cell mapping
    const int cj = tid >> 5, cb = tid & 31;
    // publish addressing for element (b=cb, k=u0+cj)
    const int pk    = u0 + cj;
    const int pslot = pk >> 4;
    const int pkk   = pk & 15;
    const int pt    = (pkk >> 1) & 3;
    const int pkreg = pkk >> 3;
    const int pbyte = pkk & 1;
    const int pmt   = cb >> 4;
    const int prh   = (cb >> 3) & 1;
    const int plane_idx = (cb & 7) * 4 + pt;
    const int preg  = pkreg * 2 + prh;

    // ---- one-time: pack W_hh rows into B-fragment smem (fp16 hi/lo) ----
    // uint4 per (slot,nt,lane): {hi_b0, hi_b1, lo_b0, lo_b1}
    for (int n = 0; n < 32; n++) {
        const long grow = (long)(n >> 3) * 1024 + u0 + (n & 7);
        const float4 v = __ldg((const float4*)(Whh + grow * 1024 + tid * 4));
        const int nt = n >> 3, gg = n & 7;
        const int k0 = tid * 4;
        const int s  = k0 >> 4;
        const float va[4] = {v.x, v.y, v.z, v.w};
#pragma unroll
        for (int p = 0; p < 2; p++) {
            const int kk   = (k0 & 15) + 2 * p;
            const int tq   = (kk >> 1) & 3;
            const int kreg = kk >> 3;
            const float a = va[2 * p], b = va[2 * p + 1];
            const __half ah = __float2half_rn(a);
            const __half bh = __float2half_rn(b);
            const __half al = __float2half_rn(a - __half2float(ah));
            const __half bl = __float2half_rn(b - __half2float(bh));
            unsigned* wp = (unsigned*)&Wfrag[(s * 4 + nt) * 32 + gg * 4 + tq];
            wp[kreg]     = packh2(ah, bh);   // hi plane
            wp[2 + kreg] = packh2(al, bl);   // lo plane
        }
    }
    if (tid == 0) s_base = *(volatile unsigned*)&g_gen2;
    __syncthreads();
    const unsigned base = s_base;

    float cst = 0.f;

#pragma unroll 1
    for (int t = 0; t < Tz; t++) {
        const float4 xwv = __ldg((const float4*)(xw + ((long)t * 32 + rb) * 4096 + xcol));

        if (t > 0) {
            const int par = (t + 1) & 1;     // buffer where h(t-1) was published

            float acc[2][4][4];
#pragma unroll
            for (int mt = 0; mt < 2; mt++)
#pragma unroll
                for (int nt = 0; nt < 4; nt++)
#pragma unroll
                    for (int q = 0; q < 4; q++) acc[mt][nt][q] = 0.f;

            const int s0 = w * 8;
            // 3-deep A-fragment prefetch ring (single fp16 plane)
            uint4 bA[3][2];
#pragma unroll
            for (int pb = 0; pb < 3; pb++) {
                bA[pb][0] = __ldcg(&g_frag[par][s0 + pb][0][lane]);
                bA[pb][1] = __ldcg(&g_frag[par][s0 + pb][1][lane]);
            }
            // 2-deep B-fragment (smem) prefetch ring
            uint4 Bf[2][4];
#pragma unroll
            for (int nt = 0; nt < 4; nt++)
                Bf[0][nt] = Wfrag[(s0 * 4 + nt) * 32 + lane];

#pragma unroll
            for (int i = 0; i < 8; i++) {
                const int s   = s0 + i;
                const int abuf = i % 3;
                const int bbuf = i & 1;

                const uint4 cA0 = bA[abuf][0], cA1 = bA[abuf][1];
                if (i < 5) {
                    bA[abuf][0] = __ldcg(&g_frag[par][s + 3][0][lane]);
                    bA[abuf][1] = __ldcg(&g_frag[par][s + 3][1][lane]);
                }
                if (i < 7) {
#pragma unroll
                    for (int nt = 0; nt < 4; nt++)
                        Bf[bbuf ^ 1][nt] = Wfrag[((s + 1) * 4 + nt) * 32 + lane];
                }

#pragma unroll
                for (int nt = 0; nt < 4; nt++) {
                    const uint4 bb = Bf[bbuf][nt];
                    MMA_F16(acc[0][nt], cA0.x, cA0.y, cA0.z, cA0.w, bb.x, bb.y);
                    MMA_F16(acc[1][nt], cA1.x, cA1.y, cA1.z, cA1.w, bb.x, bb.y);
                    MMA_F16(acc[0][nt], cA0.x, cA0.y, cA0.z, cA0.w, bb.z, bb.w);
                    MMA_F16(acc[1][nt], cA1.x, cA1.y, cA1.z, cA1.w, bb.z, bb.w);
                }
            }

            // per-warp partials -> Psm[w][b][n]
#pragma unroll
            for (int mt = 0; mt < 2; mt++) {
                const int b1 = mt * 16 + g, b2 = b1 + 8;
#pragma unroll
                for (int nt = 0; nt < 4; nt++) {
                    const int n0 = nt * 8 + 2 * th4;
                    *(float2*)&Psm[(w * 32 + b1) * 36 + n0] = make_float2(acc[mt][nt][0], acc[mt][nt][1]);
                    *(float2*)&Psm[(w * 32 + b2) * 36 + n0] = make_float2(acc[mt][nt][2], acc[mt][nt][3]);
                }
            }
        }
        __syncthreads();

        // reduce 8 warp partials + xw -> Gsm[b][n]
        float4 sum = xwv;
        if (t > 0) {
#pragma unroll
            for (int s = 0; s < 8; s++) {
                const float4 v = *(const float4*)&Psm[(s * 32 + rb) * 36 + rn4];
                sum.x += v.x; sum.y += v.y; sum.z += v.z; sum.w += v.w;
            }
        }
        *(float4*)&Gsm[rb * 36 + rn4] = sum;
        __syncthreads();

        // cell update
        const float gi = sigm     (Gsm[cb * 36 + cj]);
        const float gf = sigm     (Gsm[cb * 36 + 8 + cj]);
        const float gg2= tanh_fast(Gsm[cb * 36 + 16 + cj]);
        const float go = sigm     (Gsm[cb * 36 + 24 + cj]);
        cst = gf * cst + gi * gg2;
        const float hf = go * tanh_fast(cst);

        // publish h into fragment buffer (single fp16 plane)
        {
            const __half hh = __float2half_rn(hf);
            const int par = t & 1;
            unsigned short* bp = (unsigned short*)&g_frag[par][pslot][pmt][plane_idx];
            bp[preg * 2 + pbyte] = __half_as_ushort(hh);
        }

        // ---- grid barrier (two-hop flag barrier — proven optimum) ----
        const unsigned target = base + (unsigned)t + 1u;
        __threadfence();
        __syncthreads();
        if (tid == 0)
            *(volatile unsigned*)&g_arrive[bid] = target;
        if (bid == 0) {
            if (tid < RBLK) {
                while ((int)(*(volatile unsigned*)&g_arrive[tid] - target) < 0) {}
            }
            __syncthreads();
            if (tid == 0) {
                __threadfence();
                *(volatile unsigned*)&g_gen2 = target;
            }
        }
        if (tid == 0) {
            while ((int)(*(volatile unsigned*)&g_gen2 - target) < 0) {}
        }
        __syncthreads();

        // fp32 hidden state store off the critical path (after barrier)
        hs_out[((long)t * 32 + cb) * 1024 + u0 + cj] = hf;
    }
}

// ---------------------------------------------------------------------------------
extern "C" void kernel_launch(void* const* d_in, const int* in_sizes, int n_in,
                              void* d_out, int out_size)
{
    const float* x     = (const float*)d_in[0];
    const float* W_ih0 = (const float*)d_in[1];
    const float* W_hh0 = (const float*)d_in[2];
    const float* b_ih0 = (const float*)d_in[3];
    const float* b_hh0 = (const float*)d_in[4];
    const float* W_ih1 = (const float*)d_in[5];
    const float* W_hh1 = (const float*)d_in[6];
    const float* b_ih1 = (const float*)d_in[7];
    const float* b_hh1 = (const float*)d_in[8];
    const float* fc_w  = (const float*)d_in[9];
    const float* fc_b  = (const float*)d_in[10];
    float* out = (float*)d_out;

    float *xw, *hs0, *hs1;
    cudaGetSymbolAddress((void**)&xw,  g_xw);
    cudaGetSymbolAddress((void**)&hs0, g_hs0);
    cudaGetSymbolAddress((void**)&hs1, g_hs1);

    cudaFuncSetAttribute(lstm_rec, cudaFuncAttributeMaxDynamicSharedMemorySize, SMEM_REC);
    cudaFuncSetAttribute(gemm_tf32, cudaFuncAttributeMaxDynamicSharedMemorySize, GEMM_SMEM);

    // 1) xW0 = x @ W_ih0^T + b_ih0 + b_hh0        [16384 x 4096], K=256
    gemm_tf32<<<dim3(G4z / 128, Mz / 128), 256, GEMM_SMEM>>>(
        x, W_ih0, b_ih0, b_hh0, xw, G4z, INz, /*amode=*/1, /*omode=*/0);
    // 2) layer-0 recurrence -> hs0
    lstm_rec<<<RBLK, 256, SMEM_REC>>>(xw, W_hh0, hs0);
    // 3) xW1 = hs0 @ W_ih1^T + b_ih1 + b_hh1      [16384 x 4096], K=1024
    gemm_tf32<<<dim3(G4z / 128, Mz / 128), 256, GEMM_SMEM>>>(
        hs0, W_ih1, b_ih1, b_hh1, xw, G4z, Hz, /*amode=*/0, /*omode=*/0);
    // 4) layer-1 recurrence -> hs1
    lstm_rec<<<RBLK, 256, SMEM_REC>>>(xw, W_hh1, hs1);
    // 5) out = hs1 @ fc_w^T + fc_b                [b][t][256], K=1024
    gemm_tf32<<<dim3(OUTz / 128, Mz / 128), 256, GEMM_SMEM>>>(
        hs1, fc_w, fc_b, nullptr, out, OUTz, Hz, /*amode=*/0, /*omode=*/1);
}

// round 16
// speedup vs baseline: 1.2028x; 1.0504x over previous
#include <cuda_runtime.h>
#include <cuda_bf16.h>
#include <cuda_fp16.h>
#include <math.h>

#define Bz   32
#define Tz   512
#define INz  256
#define Hz   1024
#define G4z  4096
#define OUTz 256
#define Mz   (Bz * Tz)          // 16384

#define RBLK  128                // recurrent blocks (1/SM, all co-resident)
#define SLOTS 64                 // k16 slots covering Hz=1024

// lstm_rec smem: Wfrag uint4[64*4*32] (131072 B) + Psm f32[8*32*36] (36864 B)
//                + Gsm f32[32*36] (4608 B)
#define SMEM_REC  (131072 + 36864 + 4608)     // 172544 B

// gemm_f16 smem: As2/Bs2 uint[2][128*20] each -> 2*2*128*20*4 = 40960 B
#define GEMM_SMEM (2 * 2 * 128 * 20 * 4)

// ------------------------- device scratch (no allocs allowed) -------------------
static __device__ float  g_xw [(size_t)Mz * G4z];   // 256 MB
static __device__ float  g_hs0[(size_t)Mz * Hz];    // 64 MB
static __device__ float  g_hs1[(size_t)Mz * Hz];    // 64 MB
// h (fp16, single plane) in MMA A-fragment layout: [parity][slot][mt][lane]
static __device__ uint4    g_frag[2][SLOTS][2][32];
static __device__ unsigned g_arrive[RBLK];
static __device__ unsigned g_gen2;

__device__ __forceinline__ unsigned packh2(__half a, __half b) {
    return (unsigned)__half_as_ushort(a) | ((unsigned)__half_as_ushort(b) << 16);
}
__device__ __forceinline__ unsigned packf2h2(float a, float b) {
    return packh2(__float2half_rn(a), __float2half_rn(b));
}

#define MMA_F16(d, a0, a1, a2, a3, b0, b1)                                    \
    asm volatile("mma.sync.aligned.m16n8k16.row.col.f32.f16.f16.f32 "         \
        "{%0,%1,%2,%3}, {%4,%5,%6,%7}, {%8,%9}, {%0,%1,%2,%3};"               \
        : "+f"(d[0]), "+f"(d[1]), "+f"(d[2]), "+f"(d[3])                      \
        : "r"(a0), "r"(a1), "r"(a2), "r"(a3), "r"(b0), "r"(b1))

// ---------------------------------------------------------------------------------
// fp16 tensor-core GEMM: O[m][n] = sum_k A[m][k]*W[n][k] + bias1[n] (+bias2[n]).
// Same 128x128 tile / warp layout as the verified tf32 version; operands converted
// to fp16 (same 10-bit mantissa as tf32) at the smem stage; m16n8k16 = 2x MACs/instr.
// Single __syncthreads per k-chunk (double buffer; store->sync->compute ordering).
// ---------------------------------------------------------------------------------
__global__ void __launch_bounds__(256) gemm_f16(
    const float* __restrict__ A, const float* __restrict__ W,
    const float* __restrict__ bias1, const float* __restrict__ bias2,
    float* __restrict__ O, int N, int K, int amode, int omode)
{
    extern __shared__ unsigned gsm[];
    unsigned* Asm = gsm;                       // [2][128*20] half2 units
    unsigned* Bsm = gsm + 2 * 128 * 20;

    const int tid  = threadIdx.x;
    const int bm   = blockIdx.y * 128;
    const int bn   = blockIdx.x * 128;
    const int wid  = tid >> 5, lane = tid & 31;
    const int wm   = (wid >> 2) * 64;
    const int wn   = (wid & 3) * 32;
    const int g    = lane >> 2;
    const int t4   = lane & 3;

    const int lr = tid >> 1;             // 0..127
    const int lh = (tid & 1) * 16;       // float offset 0 or 16

    long arow;
    {
        const int m = bm + lr;
        if (amode == 1) { const int b = m & 31, t = m >> 5; arow = ((long)b * Tz + t) * (long)K; }
        else            { arow = (long)m * K; }
    }
    const long brow = (long)(bn + lr) * K;

    float acc[4][4][4];
#pragma unroll
    for (int i = 0; i < 4; i++)
#pragma unroll
        for (int j = 0; j < 4; j++)
#pragma unroll
            for (int q = 0; q < 4; q++) acc[i][j][q] = 0.f;

    float4 av[4], bv[4];
#pragma unroll
    for (int q = 0; q < 4; q++) {
        av[q] = __ldg((const float4*)(A + arow + lh + q * 4));
        bv[q] = __ldg((const float4*)(W + brow + lh + q * 4));
    }

    const int nc = K >> 5;
    for (int c = 0; c < nc; c++) {
        unsigned* as = Asm + (c & 1) * (128 * 20);
        unsigned* bs = Bsm + (c & 1) * (128 * 20);
        const int sb = lr * 20 + (lh >> 1);   // half2 index
        {
            uint4 ua0 = make_uint4(packf2h2(av[0].x, av[0].y), packf2h2(av[0].z, av[0].w),
                                   packf2h2(av[1].x, av[1].y), packf2h2(av[1].z, av[1].w));
            uint4 ua1 = make_uint4(packf2h2(av[2].x, av[2].y), packf2h2(av[2].z, av[2].w),
                                   packf2h2(av[3].x, av[3].y), packf2h2(av[3].z, av[3].w));
            uint4 ub0 = make_uint4(packf2h2(bv[0].x, bv[0].y), packf2h2(bv[0].z, bv[0].w),
                                   packf2h2(bv[1].x, bv[1].y), packf2h2(bv[1].z, bv[1].w));
            uint4 ub1 = make_uint4(packf2h2(bv[2].x, bv[2].y), packf2h2(bv[2].z, bv[2].w),
                                   packf2h2(bv[3].x, bv[3].y), packf2h2(bv[3].z, bv[3].w));
            *(uint4*)&as[sb]     = ua0;
            *(uint4*)&as[sb + 4] = ua1;
            *(uint4*)&bs[sb]     = ub0;
            *(uint4*)&bs[sb + 4] = ub1;
        }
        __syncthreads();

        if (c + 1 < nc) {
            const long ko = (long)(c + 1) * 32 + lh;
#pragma unroll
            for (int q = 0; q < 4; q++) {
                av[q] = __ldg((const float4*)(A + arow + ko + q * 4));
                bv[q] = __ldg((const float4*)(W + brow + ko + q * 4));
            }
        }

        // 32-k chunk = 2 x k16 steps; 32 MMAs per chunk
#pragma unroll
        for (int k16 = 0; k16 < 2; k16++) {
            const int kb = k16 * 8;
            unsigned af[4][4], bf[4][2];
#pragma unroll
            for (int fm = 0; fm < 4; fm++) {
                const int r0 = wm + fm * 16 + g;
                af[fm][0] = as[r0 * 20 + kb + t4];
                af[fm][1] = as[(r0 + 8) * 20 + kb + t4];
                af[fm][2] = as[r0 * 20 + kb + t4 + 4];
                af[fm][3] = as[(r0 + 8) * 20 + kb + t4 + 4];
            }
#pragma unroll
            for (int fn = 0; fn < 4; fn++) {
                const int n0 = wn + fn * 8 + g;
                bf[fn][0] = bs[n0 * 20 + kb + t4];
                bf[fn][1] = bs[n0 * 20 + kb + t4 + 4];
            }
#pragma unroll
            for (int fm = 0; fm < 4; fm++)
#pragma unroll
                for (int fn = 0; fn < 4; fn++)
                    MMA_F16(acc[fm][fn], af[fm][0], af[fm][1], af[fm][2], af[fm][3],
                            bf[fn][0], bf[fn][1]);
        }
        // no trailing sync: double buffer + store->sync->compute ordering is race-free
    }

#pragma unroll
    for (int fm = 0; fm < 4; fm++) {
        const int r0 = bm + wm + fm * 16 + g;
#pragma unroll
        for (int fn = 0; fn < 4; fn++) {
            const int n0 = bn + wn + fn * 8 + t4 * 2;
            float b0v = bias1[n0], b1v = bias1[n0 + 1];
            if (bias2) { b0v += bias2[n0]; b1v += bias2[n0 + 1]; }
            const float2 v0 = make_float2(acc[fm][fn][0] + b0v, acc[fm][fn][1] + b1v);
            const float2 v1 = make_float2(acc[fm][fn][2] + b0v, acc[fm][fn][3] + b1v);
            if (omode == 0) {
                *(float2*)&O[(long)r0 * N + n0]       = v0;
                *(float2*)&O[(long)(r0 + 8) * N + n0] = v1;
            } else {
                int b_ = r0 & 31, t_ = r0 >> 5;
                *(float2*)&O[((long)b_ * Tz + t_) * N + n0] = v0;
                b_ = (r0 + 8) & 31; t_ = (r0 + 8) >> 5;
                *(float2*)&O[((long)b_ * Tz + t_) * N + n0] = v1;
            }
        }
    }
}

// ---------------------------------------------------------------------------------
// Persistent LSTM recurrence — byte-identical to R14 (proven: 2-term fp16 split,
// 8 warps, two-hop barrier, 3-deep A prefetch, 2-deep B prefetch).
// ---------------------------------------------------------------------------------
__device__ __forceinline__ float sigm(float x) {
    return __fdividef(1.0f, 1.0f + __expf(-x));
}
__device__ __forceinline__ float tanh_fast(float x) {
    const float e = __expf(2.0f * x);
    return __fdividef(e - 1.0f, e + 1.0f);
}

__global__ void __launch_bounds__(256, 1) lstm_rec(
    const float* __restrict__ xw,      // [T*B][4096], row m = t*32+b
    const float* __restrict__ Whh,     // [4096][1024]
    float* __restrict__ hs_out)        // [T*B][1024], row m = t*32+b
{
    extern __shared__ char smraw[];
    uint4* Wfrag = (uint4*)smraw;                 // [64 slots][4 nt][32 lanes]
    float* Psm   = (float*)(smraw + 131072);      // [8 w][32 b][36]
    float* Gsm   = Psm + 8 * 32 * 36;             // [32 b][36 n]
    __shared__ unsigned s_base;

    const int tid  = threadIdx.x;
    const int bid  = blockIdx.x;
    const int u0   = bid * 8;
    const int w    = tid >> 5;
    const int lane = tid & 31;
    const int g    = lane >> 2;
    const int th4  = lane & 3;

    // reduce mapping
    const int rb   = tid >> 3;           // batch 0..31
    const int rn4  = (tid & 7) * 4;      // n group
    const long xcol = (long)(rn4 >> 3) * 1024 + u0 + (rn4 & 7);

    // cell mapping
    const int cj = tid >> 5, cb = tid & 31;
    // publish addressing for element (b=cb, k=u0+cj)
    const int pk    = u0 + cj;
    const int pslot = pk >> 4;
    const int pkk   = pk & 15;
    const int pt    = (pkk >> 1) & 3;
    const int pkreg = pkk >> 3;
    const int pbyte = pkk & 1;
    const int pmt   = cb >> 4;
    const int prh   = (cb >> 3) & 1;
    const int plane_idx = (cb & 7) * 4 + pt;
    const int preg  = pkreg * 2 + prh;

    // ---- one-time: pack W_hh rows into B-fragment smem (fp16 hi/lo) ----
    for (int n = 0; n < 32; n++) {
        const long grow = (long)(n >> 3) * 1024 + u0 + (n & 7);
        const float4 v = __ldg((const float4*)(Whh + grow * 1024 + tid * 4));
        const int nt = n >> 3, gg = n & 7;
        const int k0 = tid * 4;
        const int s  = k0 >> 4;
        const float va[4] = {v.x, v.y, v.z, v.w};
#pragma unroll
        for (int p = 0; p < 2; p++) {
            const int kk   = (k0 & 15) + 2 * p;
            const int tq   = (kk >> 1) & 3;
            const int kreg = kk >> 3;
            const float a = va[2 * p], b = va[2 * p + 1];
            const __half ah = __float2half_rn(a);
            const __half bh = __float2half_rn(b);
            const __half al = __float2half_rn(a - __half2float(ah));
            const __half bl = __float2half_rn(b - __half2float(bh));
            unsigned* wp = (unsigned*)&Wfrag[(s * 4 + nt) * 32 + gg * 4 + tq];
            wp[kreg]     = packh2(ah, bh);   // hi plane
            wp[2 + kreg] = packh2(al, bl);   // lo plane
        }
    }
    if (tid == 0) s_base = *(volatile unsigned*)&g_gen2;
    __syncthreads();
    const unsigned base = s_base;

    float cst = 0.f;

#pragma unroll 1
    for (int t = 0; t < Tz; t++) {
        const float4 xwv = __ldg((const float4*)(xw + ((long)t * 32 + rb) * 4096 + xcol));

        if (t > 0) {
            const int par = (t + 1) & 1;     // buffer where h(t-1) was published

            float acc[2][4][4];
#pragma unroll
            for (int mt = 0; mt < 2; mt++)
#pragma unroll
                for (int nt = 0; nt < 4; nt++)
#pragma unroll
                    for (int q = 0; q < 4; q++) acc[mt][nt][q] = 0.f;

            const int s0 = w * 8;
            // 3-deep A-fragment prefetch ring (single fp16 plane)
            uint4 bA[3][2];
#pragma unroll
            for (int pb = 0; pb < 3; pb++) {
                bA[pb][0] = __ldcg(&g_frag[par][s0 + pb][0][lane]);
                bA[pb][1] = __ldcg(&g_frag[par][s0 + pb][1][lane]);
            }
            // 2-deep B-fragment (smem) prefetch ring
            uint4 Bf[2][4];
#pragma unroll
            for (int nt = 0; nt < 4; nt++)
                Bf[0][nt] = Wfrag[(s0 * 4 + nt) * 32 + lane];

#pragma unroll
            for (int i = 0; i < 8; i++) {
                const int s   = s0 + i;
                const int abuf = i % 3;
                const int bbuf = i & 1;

                const uint4 cA0 = bA[abuf][0], cA1 = bA[abuf][1];
                if (i < 5) {
                    bA[abuf][0] = __ldcg(&g_frag[par][s + 3][0][lane]);
                    bA[abuf][1] = __ldcg(&g_frag[par][s + 3][1][lane]);
                }
                if (i < 7) {
#pragma unroll
                    for (int nt = 0; nt < 4; nt++)
                        Bf[bbuf ^ 1][nt] = Wfrag[((s + 1) * 4 + nt) * 32 + lane];
                }

#pragma unroll
                for (int nt = 0; nt < 4; nt++) {
                    const uint4 bb = Bf[bbuf][nt];
                    MMA_F16(acc[0][nt], cA0.x, cA0.y, cA0.z, cA0.w, bb.x, bb.y);
                    MMA_F16(acc[1][nt], cA1.x, cA1.y, cA1.z, cA1.w, bb.x, bb.y);
                    MMA_F16(acc[0][nt], cA0.x, cA0.y, cA0.z, cA0.w, bb.z, bb.w);
                    MMA_F16(acc[1][nt], cA1.x, cA1.y, cA1.z, cA1.w, bb.z, bb.w);
                }
            }

            // per-warp partials -> Psm[w][b][n]
#pragma unroll
            for (int mt = 0; mt < 2; mt++) {
                const int b1 = mt * 16 + g, b2 = b1 + 8;
#pragma unroll
                for (int nt = 0; nt < 4; nt++) {
                    const int n0 = nt * 8 + 2 * th4;
                    *(float2*)&Psm[(w * 32 + b1) * 36 + n0] = make_float2(acc[mt][nt][0], acc[mt][nt][1]);
                    *(float2*)&Psm[(w * 32 + b2) * 36 + n0] = make_float2(acc[mt][nt][2], acc[mt][nt][3]);
                }
            }
        }
        __syncthreads();

        // reduce 8 warp partials + xw -> Gsm[b][n]
        float4 sum = xwv;
        if (t > 0) {
#pragma unroll
            for (int s = 0; s < 8; s++) {
                const float4 v = *(const float4*)&Psm[(s * 32 + rb) * 36 + rn4];
                sum.x += v.x; sum.y += v.y; sum.z += v.z; sum.w += v.w;
            }
        }
        *(float4*)&Gsm[rb * 36 + rn4] = sum;
        __syncthreads();

        // cell update
        const float gi = sigm     (Gsm[cb * 36 + cj]);
        const float gf = sigm     (Gsm[cb * 36 + 8 + cj]);
        const float gg2= tanh_fast(Gsm[cb * 36 + 16 + cj]);
        const float go = sigm     (Gsm[cb * 36 + 24 + cj]);
        cst = gf * cst + gi * gg2;
        const float hf = go * tanh_fast(cst);

        // publish h into fragment buffer (single fp16 plane)
        {
            const __half hh = __float2half_rn(hf);
            const int par = t & 1;
            unsigned short* bp = (unsigned short*)&g_frag[par][pslot][pmt][plane_idx];
            bp[preg * 2 + pbyte] = __half_as_ushort(hh);
        }

        // ---- grid barrier (two-hop flag barrier — proven optimum) ----
        const unsigned target = base + (unsigned)t + 1u;
        __threadfence();
        __syncthreads();
        if (tid == 0)
            *(volatile unsigned*)&g_arrive[bid] = target;
        if (bid == 0) {
            if (tid < RBLK) {
                while ((int)(*(volatile unsigned*)&g_arrive[tid] - target) < 0) {}
            }
            __syncthreads();
            if (tid == 0) {
                __threadfence();
                *(volatile unsigned*)&g_gen2 = target;
            }
        }
        if (tid == 0) {
            while ((int)(*(volatile unsigned*)&g_gen2 - target) < 0) {}
        }
        __syncthreads();

        // fp32 hidden state store off the critical path (after barrier)
        hs_out[((long)t * 32 + cb) * 1024 + u0 + cj] = hf;
    }
}

// ---------------------------------------------------------------------------------
extern "C" void kernel_launch(void* const* d_in, const int* in_sizes, int n_in,
                              void* d_out, int out_size)
{
    const float* x     = (const float*)d_in[0];
    const float* W_ih0 = (const float*)d_in[1];
    const float* W_hh0 = (const float*)d_in[2];
    const float* b_ih0 = (const float*)d_in[3];
    const float* b_hh0 = (const float*)d_in[4];
    const float* W_ih1 = (const float*)d_in[5];
    const float* W_hh1 = (const float*)d_in[6];
    const float* b_ih1 = (const float*)d_in[7];
    const float* b_hh1 = (const float*)d_in[8];
    const float* fc_w  = (const float*)d_in[9];
    const float* fc_b  = (const float*)d_in[10];
    float* out = (float*)d_out;

    float *xw, *hs0, *hs1;
    cudaGetSymbolAddress((void**)&xw,  g_xw);
    cudaGetSymbolAddress((void**)&hs0, g_hs0);
    cudaGetSymbolAddress((void**)&hs1, g_hs1);

    cudaFuncSetAttribute(lstm_rec, cudaFuncAttributeMaxDynamicSharedMemorySize, SMEM_REC);
    cudaFuncSetAttribute(gemm_f16, cudaFuncAttributeMaxDynamicSharedMemorySize, GEMM_SMEM);

    // 1) xW0 = x @ W_ih0^T + b_ih0 + b_hh0        [16384 x 4096], K=256
    gemm_f16<<<dim3(G4z / 128, Mz / 128), 256, GEMM_SMEM>>>(
        x, W_ih0, b_ih0, b_hh0, xw, G4z, INz, /*amode=*/1, /*omode=*/0);
    // 2) layer-0 recurrence -> hs0
    lstm_rec<<<RBLK, 256, SMEM_REC>>>(xw, W_hh0, hs0);
    // 3) xW1 = hs0 @ W_ih1^T + b_ih1 + b_hh1      [16384 x 4096], K=1024
    gemm_f16<<<dim3(G4z / 128, Mz / 128), 256, GEMM_SMEM>>>(
        hs0, W_ih1, b_ih1, b_hh1, xw, G4z, Hz, /*amode=*/0, /*omode=*/0);
    // 4) layer-1 recurrence -> hs1
    lstm_rec<<<RBLK, 256, SMEM_REC>>>(xw, W_hh1, hs1);
    // 5) out = hs1 @ fc_w^T + fc_b                [b][t][256], K=1024
    gemm_f16<<<dim3(OUTz / 128, Mz / 128), 256, GEMM_SMEM>>>(
        hs1, fc_w, fc_b, nullptr, out, OUTz, Hz, /*amode=*/0, /*omode=*/1);
}

// round 17
// speedup vs baseline: 1.3158x; 1.0940x over previous
#include <cuda_runtime.h>
#include <cuda_bf16.h>
#include <cuda_fp16.h>
#include <math.h>

#define Bz   32
#define Tz   512
#define INz  256
#define Hz   1024
#define G4z  4096
#define OUTz 256
#define Mz   (Bz * Tz)          // 16384

#define RBLK  128                // recurrent blocks (1/SM, all co-resident)
#define SLOTS 64                 // k16 slots covering Hz=1024

// lstm_rec smem: Wfrag uint2[64*4*32] (65536 B) + Psm f32[8*32*36] (36864 B)
//                + Gsm f32[32*36] (4608 B)
#define SMEM_REC  (65536 + 36864 + 4608)      // 107008 B

// gemm_f16 smem: As2/Bs2 uint[2][128*20] each -> 2*2*128*20*4 = 40960 B
#define GEMM_SMEM (2 * 2 * 128 * 20 * 4)

// ------------------------- device scratch (no allocs allowed) -------------------
static __device__ float  g_xw [(size_t)Mz * G4z];   // 256 MB
static __device__ float  g_hs0[(size_t)Mz * Hz];    // 64 MB
static __device__ float  g_hs1[(size_t)Mz * Hz];    // 64 MB
// h (fp16, single plane) in MMA A-fragment layout: [parity][slot][mt][lane]
static __device__ uint4    g_frag[2][SLOTS][2][32];
static __device__ unsigned g_arrive[RBLK];
static __device__ unsigned g_gen2;

__device__ __forceinline__ unsigned packh2(__half a, __half b) {
    return (unsigned)__half_as_ushort(a) | ((unsigned)__half_as_ushort(b) << 16);
}
__device__ __forceinline__ unsigned packf2h2(float a, float b) {
    return packh2(__float2half_rn(a), __float2half_rn(b));
}

#define MMA_F16(d, a0, a1, a2, a3, b0, b1)                                    \
    asm volatile("mma.sync.aligned.m16n8k16.row.col.f32.f16.f16.f32 "         \
        "{%0,%1,%2,%3}, {%4,%5,%6,%7}, {%8,%9}, {%0,%1,%2,%3};"               \
        : "+f"(d[0]), "+f"(d[1]), "+f"(d[2]), "+f"(d[3])                      \
        : "r"(a0), "r"(a1), "r"(a2), "r"(a3), "r"(b0), "r"(b1))

// ---------------------------------------------------------------------------------
// fp16 tensor-core GEMM — byte-identical to R15 (verified).
// ---------------------------------------------------------------------------------
__global__ void __launch_bounds__(256) gemm_f16(
    const float* __restrict__ A, const float* __restrict__ W,
    const float* __restrict__ bias1, const float* __restrict__ bias2,
    float* __restrict__ O, int N, int K, int amode, int omode)
{
    extern __shared__ unsigned gsm[];
    unsigned* Asm = gsm;                       // [2][128*20] half2 units
    unsigned* Bsm = gsm + 2 * 128 * 20;

    const int tid  = threadIdx.x;
    const int bm   = blockIdx.y * 128;
    const int bn   = blockIdx.x * 128;
    const int wid  = tid >> 5, lane = tid & 31;
    const int wm   = (wid >> 2) * 64;
    const int wn   = (wid & 3) * 32;
    const int g    = lane >> 2;
    const int t4   = lane & 3;

    const int lr = tid >> 1;             // 0..127
    const int lh = (tid & 1) * 16;       // float offset 0 or 16

    long arow;
    {
        const int m = bm + lr;
        if (amode == 1) { const int b = m & 31, t = m >> 5; arow = ((long)b * Tz + t) * (long)K; }
        else            { arow = (long)m * K; }
    }
    const long brow = (long)(bn + lr) * K;

    float acc[4][4][4];
#pragma unroll
    for (int i = 0; i < 4; i++)
#pragma unroll
        for (int j = 0; j < 4; j++)
#pragma unroll
            for (int q = 0; q < 4; q++) acc[i][j][q] = 0.f;

    float4 av[4], bv[4];
#pragma unroll
    for (int q = 0; q < 4; q++) {
        av[q] = __ldg((const float4*)(A + arow + lh + q * 4));
        bv[q] = __ldg((const float4*)(W + brow + lh + q * 4));
    }

    const int nc = K >> 5;
    for (int c = 0; c < nc; c++) {
        unsigned* as = Asm + (c & 1) * (128 * 20);
        unsigned* bs = Bsm + (c & 1) * (128 * 20);
        const int sb = lr * 20 + (lh >> 1);   // half2 index
        {
            uint4 ua0 = make_uint4(packf2h2(av[0].x, av[0].y), packf2h2(av[0].z, av[0].w),
                                   packf2h2(av[1].x, av[1].y), packf2h2(av[1].z, av[1].w));
            uint4 ua1 = make_uint4(packf2h2(av[2].x, av[2].y), packf2h2(av[2].z, av[2].w),
                                   packf2h2(av[3].x, av[3].y), packf2h2(av[3].z, av[3].w));
            uint4 ub0 = make_uint4(packf2h2(bv[0].x, bv[0].y), packf2h2(bv[0].z, bv[0].w),
                                   packf2h2(bv[1].x, bv[1].y), packf2h2(bv[1].z, bv[1].w));
            uint4 ub1 = make_uint4(packf2h2(bv[2].x, bv[2].y), packf2h2(bv[2].z, bv[2].w),
                                   packf2h2(bv[3].x, bv[3].y), packf2h2(bv[3].z, bv[3].w));
            *(uint4*)&as[sb]     = ua0;
            *(uint4*)&as[sb + 4] = ua1;
            *(uint4*)&bs[sb]     = ub0;
            *(uint4*)&bs[sb + 4] = ub1;
        }
        __syncthreads();

        if (c + 1 < nc) {
            const long ko = (long)(c + 1) * 32 + lh;
#pragma unroll
            for (int q = 0; q < 4; q++) {
                av[q] = __ldg((const float4*)(A + arow + ko + q * 4));
                bv[q] = __ldg((const float4*)(W + brow + ko + q * 4));
            }
        }

        // 32-k chunk = 2 x k16 steps; 32 MMAs per chunk
#pragma unroll
        for (int k16 = 0; k16 < 2; k16++) {
            const int kb = k16 * 8;
            unsigned af[4][4], bf[4][2];
#pragma unroll
            for (int fm = 0; fm < 4; fm++) {
                const int r0 = wm + fm * 16 + g;
                af[fm][0] = as[r0 * 20 + kb + t4];
                af[fm][1] = as[(r0 + 8) * 20 + kb + t4];
                af[fm][2] = as[r0 * 20 + kb + t4 + 4];
                af[fm][3] = as[(r0 + 8) * 20 + kb + t4 + 4];
            }
#pragma unroll
            for (int fn = 0; fn < 4; fn++) {
                const int n0 = wn + fn * 8 + g;
                bf[fn][0] = bs[n0 * 20 + kb + t4];
                bf[fn][1] = bs[n0 * 20 + kb + t4 + 4];
            }
#pragma unroll
            for (int fm = 0; fm < 4; fm++)
#pragma unroll
                for (int fn = 0; fn < 4; fn++)
                    MMA_F16(acc[fm][fn], af[fm][0], af[fm][1], af[fm][2], af[fm][3],
                            bf[fn][0], bf[fn][1]);
        }
        // no trailing sync: double buffer + store->sync->compute ordering is race-free
    }

#pragma unroll
    for (int fm = 0; fm < 4; fm++) {
        const int r0 = bm + wm + fm * 16 + g;
#pragma unroll
        for (int fn = 0; fn < 4; fn++) {
            const int n0 = bn + wn + fn * 8 + t4 * 2;
            float b0v = bias1[n0], b1v = bias1[n0 + 1];
            if (bias2) { b0v += bias2[n0]; b1v += bias2[n0 + 1]; }
            const float2 v0 = make_float2(acc[fm][fn][0] + b0v, acc[fm][fn][1] + b1v);
            const float2 v1 = make_float2(acc[fm][fn][2] + b0v, acc[fm][fn][3] + b1v);
            if (omode == 0) {
                *(float2*)&O[(long)r0 * N + n0]       = v0;
                *(float2*)&O[(long)(r0 + 8) * N + n0] = v1;
            } else {
                int b_ = r0 & 31, t_ = r0 >> 5;
                *(float2*)&O[((long)b_ * Tz + t_) * N + n0] = v0;
                b_ = (r0 + 8) & 31; t_ = (r0 + 8) >> 5;
                *(float2*)&O[((long)b_ * Tz + t_) * N + n0] = v1;
            }
        }
    }
}

// ---------------------------------------------------------------------------------
// Persistent LSTM recurrence — R15 structure with SINGLE-PLANE fp16 W:
// D = W_f16 @ h_f16 (one MMA per (mt,nt,slot); 64 MMAs/warp/step, was 128).
// W quantization 2^-11 relative — anchored acceptable by R14's h-fp16 result.
// ---------------------------------------------------------------------------------
__device__ __forceinline__ float sigm(float x) {
    return __fdividef(1.0f, 1.0f + __expf(-x));
}
__device__ __forceinline__ float tanh_fast(float x) {
    const float e = __expf(2.0f * x);
    return __fdividef(e - 1.0f, e + 1.0f);
}

__global__ void __launch_bounds__(256, 1) lstm_rec(
    const float* __restrict__ xw,      // [T*B][4096], row m = t*32+b
    const float* __restrict__ Whh,     // [4096][1024]
    float* __restrict__ hs_out)        // [T*B][1024], row m = t*32+b
{
    extern __shared__ char smraw[];
    uint2* Wfrag = (uint2*)smraw;                 // [64 slots][4 nt][32 lanes]
    float* Psm   = (float*)(smraw + 65536);       // [8 w][32 b][36]
    float* Gsm   = Psm + 8 * 32 * 36;             // [32 b][36 n]
    __shared__ unsigned s_base;

    const int tid  = threadIdx.x;
    const int bid  = blockIdx.x;
    const int u0   = bid * 8;
    const int w    = tid >> 5;
    const int lane = tid & 31;
    const int g    = lane >> 2;
    const int th4  = lane & 3;

    // reduce mapping
    const int rb   = tid >> 3;           // batch 0..31
    const int rn4  = (tid & 7) * 4;      // n group
    const long xcol = (long)(rn4 >> 3) * 1024 + u0 + (rn4 & 7);

    // cell mapping
    const int cj = tid >> 5, cb = tid & 31;
    // publish addressing for element (b=cb, k=u0+cj)
    const int pk    = u0 + cj;
    const int pslot = pk >> 4;
    const int pkk   = pk & 15;
    const int pt    = (pkk >> 1) & 3;
    const int pkreg = pkk >> 3;
    const int pbyte = pkk & 1;
    const int pmt   = cb >> 4;
    const int prh   = (cb >> 3) & 1;
    const int plane_idx = (cb & 7) * 4 + pt;
    const int preg  = pkreg * 2 + prh;

    // ---- one-time: pack W_hh rows into B-fragment smem (single fp16 plane) ----
    for (int n = 0; n < 32; n++) {
        const long grow = (long)(n >> 3) * 1024 + u0 + (n & 7);
        const float4 v = __ldg((const float4*)(Whh + grow * 1024 + tid * 4));
        const int nt = n >> 3, gg = n & 7;
        const int k0 = tid * 4;
        const int s  = k0 >> 4;
        const float va[4] = {v.x, v.y, v.z, v.w};
#pragma unroll
        for (int p = 0; p < 2; p++) {
            const int kk   = (k0 & 15) + 2 * p;
            const int tq   = (kk >> 1) & 3;
            const int kreg = kk >> 3;
            unsigned* wp = (unsigned*)&Wfrag[(s * 4 + nt) * 32 + gg * 4 + tq];
            wp[kreg] = packf2h2(va[2 * p], va[2 * p + 1]);
        }
    }
    if (tid == 0) s_base = *(volatile unsigned*)&g_gen2;
    __syncthreads();
    const unsigned base = s_base;

    float cst = 0.f;

#pragma unroll 1
    for (int t = 0; t < Tz; t++) {
        const float4 xwv = __ldg((const float4*)(xw + ((long)t * 32 + rb) * 4096 + xcol));

        if (t > 0) {
            const int par = (t + 1) & 1;     // buffer where h(t-1) was published

            float acc[2][4][4];
#pragma unroll
            for (int mt = 0; mt < 2; mt++)
#pragma unroll
                for (int nt = 0; nt < 4; nt++)
#pragma unroll
                    for (int q = 0; q < 4; q++) acc[mt][nt][q] = 0.f;

            const int s0 = w * 8;
            // 3-deep A-fragment prefetch ring (single fp16 plane)
            uint4 bA[3][2];
#pragma unroll
            for (int pb = 0; pb < 3; pb++) {
                bA[pb][0] = __ldcg(&g_frag[par][s0 + pb][0][lane]);
                bA[pb][1] = __ldcg(&g_frag[par][s0 + pb][1][lane]);
            }
            // 2-deep B-fragment (smem) prefetch ring
            uint2 Bf[2][4];
#pragma unroll
            for (int nt = 0; nt < 4; nt++)
                Bf[0][nt] = Wfrag[(s0 * 4 + nt) * 32 + lane];

#pragma unroll
            for (int i = 0; i < 8; i++) {
                const int s   = s0 + i;
                const int abuf = i % 3;
                const int bbuf = i & 1;

                const uint4 cA0 = bA[abuf][0], cA1 = bA[abuf][1];
                if (i < 5) {
                    bA[abuf][0] = __ldcg(&g_frag[par][s + 3][0][lane]);
                    bA[abuf][1] = __ldcg(&g_frag[par][s + 3][1][lane]);
                }
                if (i < 7) {
#pragma unroll
                    for (int nt = 0; nt < 4; nt++)
                        Bf[bbuf ^ 1][nt] = Wfrag[((s + 1) * 4 + nt) * 32 + lane];
                }

#pragma unroll
                for (int nt = 0; nt < 4; nt++) {
                    const uint2 bb = Bf[bbuf][nt];
                    MMA_F16(acc[0][nt], cA0.x, cA0.y, cA0.z, cA0.w, bb.x, bb.y);
                    MMA_F16(acc[1][nt], cA1.x, cA1.y, cA1.z, cA1.w, bb.x, bb.y);
                }
            }

            // per-warp partials -> Psm[w][b][n]
#pragma unroll
            for (int mt = 0; mt < 2; mt++) {
                const int b1 = mt * 16 + g, b2 = b1 + 8;
#pragma unroll
                for (int nt = 0; nt < 4; nt++) {
                    const int n0 = nt * 8 + 2 * th4;
                    *(float2*)&Psm[(w * 32 + b1) * 36 + n0] = make_float2(acc[mt][nt][0], acc[mt][nt][1]);
                    *(float2*)&Psm[(w * 32 + b2) * 36 + n0] = make_float2(acc[mt][nt][2], acc[mt][nt][3]);
                }
            }
        }
        __syncthreads();

        // reduce 8 warp partials + xw -> Gsm[b][n]
        float4 sum = xwv;
        if (t > 0) {
#pragma unroll
            for (int s = 0; s < 8; s++) {
                const float4 v = *(const float4*)&Psm[(s * 32 + rb) * 36 + rn4];
                sum.x += v.x; sum.y += v.y; sum.z += v.z; sum.w += v.w;
            }
        }
        *(float4*)&Gsm[rb * 36 + rn4] = sum;
        __syncthreads();

        // cell update
        const float gi = sigm     (Gsm[cb * 36 + cj]);
        const float gf = sigm     (Gsm[cb * 36 + 8 + cj]);
        const float gg2= tanh_fast(Gsm[cb * 36 + 16 + cj]);
        const float go = sigm     (Gsm[cb * 36 + 24 + cj]);
        cst = gf * cst + gi * gg2;
        const float hf = go * tanh_fast(cst);

        // publish h into fragment buffer (single fp16 plane)
        {
            const __half hh = __float2half_rn(hf);
            const int par = t & 1;
            unsigned short* bp = (unsigned short*)&g_frag[par][pslot][pmt][plane_idx];
            bp[preg * 2 + pbyte] = __half_as_ushort(hh);
        }

        // ---- grid barrier (two-hop flag barrier — proven optimum) ----
        const unsigned target = base + (unsigned)t + 1u;
        __threadfence();
        __syncthreads();
        if (tid == 0)
            *(volatile unsigned*)&g_arrive[bid] = target;
        if (bid == 0) {
            if (tid < RBLK) {
                while ((int)(*(volatile unsigned*)&g_arrive[tid] - target) < 0) {}
            }
            __syncthreads();
            if (tid == 0) {
                __threadfence();
                *(volatile unsigned*)&g_gen2 = target;
            }
        }
        if (tid == 0) {
            while ((int)(*(volatile unsigned*)&g_gen2 - target) < 0) {}
        }
        __syncthreads();

        // fp32 hidden state store off the critical path (after barrier)
        hs_out[((long)t * 32 + cb) * 1024 + u0 + cj] = hf;
    }
}

// ---------------------------------------------------------------------------------
extern "C" void kernel_launch(void* const* d_in, const int* in_sizes, int n_in,
                              void* d_out, int out_size)
{
    const float* x     = (const float*)d_in[0];
    const float* W_ih0 = (const float*)d_in[1];
    const float* W_hh0 = (const float*)d_in[2];
    const float* b_ih0 = (const float*)d_in[3];
    const float* b_hh0 = (const float*)d_in[4];
    const float* W_ih1 = (const float*)d_in[5];
    const float* W_hh1 = (const float*)d_in[6];
    const float* b_ih1 = (const float*)d_in[7];
    const float* b_hh1 = (const float*)d_in[8];
    const float* fc_w  = (const float*)d_in[9];
    const float* fc_b  = (const float*)d_in[10];
    float* out = (float*)d_out;

    float *xw, *hs0, *hs1;
    cudaGetSymbolAddress((void**)&xw,  g_xw);
    cudaGetSymbolAddress((void**)&hs0, g_hs0);
    cudaGetSymbolAddress((void**)&hs1, g_hs1);

    cudaFuncSetAttribute(lstm_rec, cudaFuncAttributeMaxDynamicSharedMemorySize, SMEM_REC);
    cudaFuncSetAttribute(gemm_f16, cudaFuncAttributeMaxDynamicSharedMemorySize, GEMM_SMEM);

    // 1) xW0 = x @ W_ih0^T + b_ih0 + b_hh0        [16384 x 4096], K=256
    gemm_f16<<<dim3(G4z / 128, Mz / 128), 256, GEMM_SMEM>>>(
        x, W_ih0, b_ih0, b_hh0, xw, G4z, INz, /*amode=*/1, /*omode=*/0);
    // 2) layer-0 recurrence -> hs0
    lstm_rec<<<RBLK, 256, SMEM_REC>>>(xw, W_hh0, hs0);
    // 3) xW1 = hs0 @ W_ih1^T + b_ih1 + b_hh1      [16384 x 4096], K=1024
    gemm_f16<<<dim3(G4z / 128, Mz / 128), 256, GEMM_SMEM>>>(
        hs0, W_ih1, b_ih1, b_hh1, xw, G4z, Hz, /*amode=*/0, /*omode=*/0);
    // 4) layer-1 recurrence -> hs1
    lstm_rec<<<RBLK, 256, SMEM_REC>>>(xw, W_hh1, hs1);
    // 5) out = hs1 @ fc_w^T + fc_b                [b][t][256], K=1024
    gemm_f16<<<dim3(OUTz / 128, Mz / 128), 256, GEMM_SMEM>>>(
        hs1, fc_w, fc_b, nullptr, out, OUTz, Hz, /*amode=*/0, /*omode=*/1);
}